// round 16
// baseline (speedup 1.0000x reference)
#include <cuda_runtime.h>
#include <cuda_bf16.h>
#include <math.h>
#include <stdint.h>

// Problem dims
#define BB 8
#define LL_ 512
#define DD 768
#define HH 12
#define MTOT 96      // BB*HH
#define NN 512

// Output layout (flattened tuple concat)
#define OFF_CTX 0
#define OFF_D   37748736
#define OFF_D0  62914560
#define OFF_LOSS 62963712

// ---------------- scratch (device globals; no allocations allowed) ----------------
__device__ float g_R[BB * LL_];
__device__ float g_m[BB * LL_];
__device__ float g_A[MTOT * NN * NN];     // exp(scores)
__device__ float g_LLm[MTOT * NN * NN];   // Laplacian -> becomes inverse in place
__device__ float g_diag[MTOT * NN];
__device__ float g_bce[BB * LL_];
// bf16 split scratch
__device__ __nv_bfloat16 g_dh[MTOT * NN * NN];   // masked d, hi
__device__ __nv_bfloat16 g_dl[MTOT * NN * NN];   // masked d, lo
__device__ __nv_bfloat16 g_xh[BB * LL_ * DD];
__device__ __nv_bfloat16 g_xl[BB * LL_ * DD];
__device__ __nv_bfloat16 g_qh[BB * LL_ * DD];
__device__ __nv_bfloat16 g_ql[BB * LL_ * DD];
__device__ __nv_bfloat16 g_kh[BB * LL_ * DD];
__device__ __nv_bfloat16 g_kl[BB * LL_ * DD];
__device__ __nv_bfloat16 g_wqh[DD * DD];
__device__ __nv_bfloat16 g_wql[DD * DD];
__device__ __nv_bfloat16 g_wkh[DD * DD];
__device__ __nv_bfloat16 g_wkl[DD * DD];
__device__ __nv_bfloat16 g_Fh[MTOT * NN * 64];   // GJ column panel hi/lo
__device__ __nv_bfloat16 g_Fl[MTOT * NN * 64];
__device__ __nv_bfloat16 g_rowh[MTOT * 64 * NN]; // GJ scaled row panel hi/lo
__device__ __nv_bfloat16 g_rowl[MTOT * 64 * NN];

// ===================== mma.sync helpers (HMMA path; compute_103-safe) =====================
__device__ __forceinline__ uint32_t smem_u32(const void* p) {
    uint32_t a;
    asm("{ .reg .u64 t; cvta.to.shared.u64 t, %1; cvt.u32.u64 %0, t; }"
        : "=r"(a) : "l"(p));
    return a;
}

__device__ __forceinline__ void ldsm4(uint32_t* r, uint32_t addr) {
    asm volatile("ldmatrix.sync.aligned.m8n8.x4.shared.b16 {%0,%1,%2,%3}, [%4];"
                 : "=r"(r[0]), "=r"(r[1]), "=r"(r[2]), "=r"(r[3]) : "r"(addr));
}
__device__ __forceinline__ void ldsm4t(uint32_t* r, uint32_t addr) {
    asm volatile("ldmatrix.sync.aligned.m8n8.x4.trans.shared.b16 {%0,%1,%2,%3}, [%4];"
                 : "=r"(r[0]), "=r"(r[1]), "=r"(r[2]), "=r"(r[3]) : "r"(addr));
}

__device__ __forceinline__ void mma16816(float* c, const uint32_t* a,
                                         uint32_t b0, uint32_t b1) {
    asm volatile("mma.sync.aligned.m16n8k16.row.col.f32.bf16.bf16.f32 "
                 "{%0,%1,%2,%3}, {%4,%5,%6,%7}, {%8,%9}, {%0,%1,%2,%3};"
                 : "+f"(c[0]), "+f"(c[1]), "+f"(c[2]), "+f"(c[3])
                 : "r"(a[0]), "r"(a[1]), "r"(a[2]), "r"(a[3]), "r"(b0), "r"(b1));
}

__device__ __forceinline__ void cp16(uint32_t dst, const void* src) {
    asm volatile("{ .reg .u64 g; cvta.to.global.u64 g, %1; "
                 "cp.async.cg.shared.global [%0], [g], 16; }"
                 :: "r"(dst), "l"(src) : "memory");
}
#define CP_COMMIT() asm volatile("cp.async.commit_group;" ::: "memory")
#define CP_WAIT0()  asm volatile("cp.async.wait_group 0;" ::: "memory")
#define CP_WAIT1()  asm volatile("cp.async.wait_group 1;" ::: "memory")

__device__ __forceinline__ void split_bf16(float v, __nv_bfloat16* h, __nv_bfloat16* l) {
    __nv_bfloat16 hh = __float2bfloat16(v);
    *h = hh;
    *l = __float2bfloat16(v - __bfloat162float(hh));
}
__device__ __forceinline__ void split2(float v0, float v1, uint32_t* hp, uint32_t* lp) {
    __nv_bfloat16 h0, l0, h1, l1;
    split_bf16(v0, &h0, &l0);
    split_bf16(v1, &h1, &l1);
    *hp = (uint32_t)__bfloat16_as_ushort(h0) | ((uint32_t)__bfloat16_as_ushort(h1) << 16);
    *lp = (uint32_t)__bfloat16_as_ushort(l0) | ((uint32_t)__bfloat16_as_ushort(l1) << 16);
}

// ---------------- x -> bf16 hi/lo ----------------
__global__ void k_xsplit(const float* __restrict__ X)
{
    int idx = blockIdx.x * 256 + threadIdx.x;
    float v = X[idx];
    __nv_bfloat16 h, l;
    split_bf16(v, &h, &l);
    g_xh[idx] = h; g_xl[idx] = l;
}

// ---------------- Wq/Wk -> bf16 hi/lo ----------------
__global__ void k_wsplit(const float* __restrict__ Wq, const float* __restrict__ Wk)
{
    int idx = blockIdx.x * 256 + threadIdx.x;   // 2*768*768
    int which = idx >= DD * DD;
    int i = which ? idx - DD * DD : idx;
    float v = which ? Wk[i] : Wq[i];
    __nv_bfloat16 h, l;
    split_bf16(v, &h, &l);
    if (which) { g_wkh[i] = h; g_wkl[i] = l; }
    else       { g_wqh[i] = h; g_wql[i] = l; }
}

// ---------------- root scores + mask precompute ----------------
__global__ __launch_bounds__(256) void k_root(const float* __restrict__ X,
                                              const float* __restrict__ Wr,
                                              const float* __restrict__ br,
                                              const float* __restrict__ mask)
{
    int warp = (blockIdx.x * blockDim.x + threadIdx.x) >> 5;
    int lane = threadIdx.x & 31;
    if (warp >= BB * LL_) return;
    float s = 0.f;
    for (int t = lane; t < 768; t += 32) s += X[warp * 768 + t] * Wr[t];
#pragma unroll
    for (int o = 16; o > 0; o >>= 1) s += __shfl_down_sync(0xffffffff, s, o);
    if (lane == 0) {
        float m = mask[warp] * (-1.0f / 10000.0f);
        float root = fmaxf(s + br[0] - m * 50.0f, -40.0f);
        g_R[warp] = expf(root);
        g_m[warp] = m;
    }
}

// ---------------- projection via HMMA split: q/k = split((X@W + b)*scale) ----------------
// Tile 64(m) x 128(n), K-chunk 32 (24 chunks). 8 warps, warp tile 16 x 64.
__global__ __launch_bounds__(256) void k_proj_mma(const float* __restrict__ bq,
                                                  const float* __restrict__ bk)
{
    __shared__ __align__(128) uint8_t sAh[8192], sAl[8192], sBh[16384], sBl[16384];
    int t = threadIdx.x;
    int which = blockIdx.z;
    int m0 = blockIdx.y * 64, n0 = blockIdx.x * 128;
    const __nv_bfloat16* Wh = which ? g_wkh : g_wqh;
    const __nv_bfloat16* Wl = which ? g_wkl : g_wql;
    const float* bias = which ? bk : bq;
    float scale = which ? 1.0f : 0.03608439182435161f;   // 1/sqrt(768)
    __nv_bfloat16* dsth = which ? g_kh : g_qh;
    __nv_bfloat16* dstl = which ? g_kl : g_ql;

    uint32_t aH = smem_u32(sAh), aL = smem_u32(sAl);
    uint32_t bH = smem_u32(sBh), bL = smem_u32(sBl);

    int wid = t >> 5, lane = t & 31;
    int wm = (wid & 3) * 16, wn = (wid >> 2) * 64;
    int lrow = (lane & 7) + ((lane >> 4) << 3);
    int lcol8 = (lane & 8) >> 3;

    float c[8][4];
#pragma unroll
    for (int j = 0; j < 8; j++)
#pragma unroll
        for (int v = 0; v < 4; v++) c[j][v] = 0.f;

    for (int kc = 0; kc < 24; kc++) {
        int k0 = kc * 32;
#pragma unroll
        for (int rep = 0; rep < 6; rep++) {
            int id = t + rep * 256;   // 0..1535
            if (id < 512) {
                int buf = id >> 8, idx = id & 255;
                int r = idx >> 2, ch = idx & 3;
                uint32_t off = (uint32_t)(r << 7) + (uint32_t)((ch ^ (r & 7)) << 4);
                cp16((buf ? aL : aH) + off,
                     (buf ? g_xl : g_xh) + (size_t)(m0 + r) * DD + k0 + ch * 8);
            } else {
                int id2 = id - 512;
                int buf = id2 >> 9, idx = id2 & 511;
                int r = idx >> 4, ch = idx & 15;
                uint32_t off = (uint32_t)(r << 8) + (uint32_t)((ch ^ (r & 7)) << 4);
                cp16((buf ? bL : bH) + off,
                     (buf ? Wl : Wh) + (size_t)(k0 + r) * DD + n0 + ch * 8);
            }
        }
        CP_COMMIT(); CP_WAIT0();
        __syncthreads();

#pragma unroll
        for (int ks = 0; ks < 2; ks++) {
            uint32_t ah[4], al[4];
            {
                int arow = wm + (lane & 15);
                int ach = ks * 2 + (lane >> 4);
                uint32_t aoff = (uint32_t)(arow << 7) + (uint32_t)((ach ^ (arow & 7)) << 4);
                ldsm4(ah, aH + aoff);
                ldsm4(al, aL + aoff);
            }
            uint32_t bhf[4][4], blf[4][4];
            int r = ks * 16 + lrow;
            int rx = r & 7;
#pragma unroll
            for (int ng = 0; ng < 4; ng++) {
                int colc = ((wn + ng * 16) >> 3) + lcol8;
                uint32_t boff = (uint32_t)(r << 8) + (uint32_t)((colc ^ rx) << 4);
                ldsm4t(bhf[ng], bH + boff);
                ldsm4t(blf[ng], bL + boff);
            }
#pragma unroll
            for (int ng = 0; ng < 4; ng++)
#pragma unroll
                for (int h = 0; h < 2; h++) {
                    int nt = ng * 2 + h;
                    mma16816(c[nt], ah, bhf[ng][h], bhf[ng][2 + h]);
                    mma16816(c[nt], ah, blf[ng][h], blf[ng][2 + h]);
                    mma16816(c[nt], al, bhf[ng][h], bhf[ng][2 + h]);
                }
        }
        __syncthreads();
    }

    int row = m0 + wm + (lane >> 2);
#pragma unroll
    for (int nt = 0; nt < 8; nt++) {
        int col = n0 + wn + nt * 8 + (lane & 3) * 2;
        float b0 = bias[col], b1 = bias[col + 1];
        uint32_t hp, lp;
        split2((c[nt][0] + b0) * scale, (c[nt][1] + b1) * scale, &hp, &lp);
        *(uint32_t*)&dsth[(size_t)row * DD + col] = hp;
        *(uint32_t*)&dstl[(size_t)row * DD + col] = lp;
        split2((c[nt][2] + b0) * scale, (c[nt][3] + b1) * scale, &hp, &lp);
        *(uint32_t*)&dsth[(size_t)(row + 8) * DD + col] = hp;
        *(uint32_t*)&dstl[(size_t)(row + 8) * DD + col] = lp;
    }
}

// ---------------- scores via HMMA split: A = exp(clip(q.k^T - masks, -40)); LL = -A ----
__global__ __launch_bounds__(256) void k_scores_mma()
{
    __shared__ __align__(128) uint8_t sQh[8192], sQl[8192], sKh[8192], sKl[8192];
    int t = threadIdx.x;
    int m = blockIdx.z, b = m / HH, h = m % HH;
    int i0 = blockIdx.y * 128, j0 = blockIdx.x * 128;
    size_t qbase = (size_t)b * LL_ * DD + h * 64;

    uint32_t qH = smem_u32(sQh), qL = smem_u32(sQl);
    uint32_t kH = smem_u32(sKh), kL = smem_u32(sKl);

    int wid = t >> 5, lane = t & 31;
    int wm = (wid & 3) * 32, wn = (wid >> 2) * 64;

    float c[2][8][4];
#pragma unroll
    for (int i = 0; i < 2; i++)
#pragma unroll
        for (int j = 0; j < 8; j++)
#pragma unroll
            for (int v = 0; v < 4; v++) c[i][j][v] = 0.f;

    for (int kc = 0; kc < 2; kc++) {
        int k0 = kc * 32;
#pragma unroll
        for (int rep = 0; rep < 8; rep++) {
            int id = t + rep * 256;
            int half = id >> 10;          // 0=Q, 1=K
            int buf = (id >> 9) & 1;      // 0=hi, 1=lo
            int idx = id & 511;
            int r = idx >> 2, ch = idx & 3;
            uint32_t off = (uint32_t)(r << 6) + (uint32_t)((ch ^ (r & 3)) << 4);
            const __nv_bfloat16* src;
            uint32_t dst;
            if (half == 0) {
                src = (buf ? g_ql : g_qh) + qbase + (size_t)(i0 + r) * DD + k0 + ch * 8;
                dst = (buf ? qL : qH) + off;
            } else {
                src = (buf ? g_kl : g_kh) + qbase + (size_t)(j0 + r) * DD + k0 + ch * 8;
                dst = (buf ? kL : kH) + off;
            }
            cp16(dst, src);
        }
        CP_COMMIT(); CP_WAIT0();
        __syncthreads();

#pragma unroll
        for (int ks = 0; ks < 2; ks++) {
            uint32_t ah[2][4], al[2][4];
#pragma unroll
            for (int sub = 0; sub < 2; sub++) {
                int arow = wm + sub * 16 + (lane & 15);
                int ach = ks * 2 + (lane >> 4);
                uint32_t aoff = (uint32_t)(arow << 6) + (uint32_t)((ach ^ (arow & 3)) << 4);
                ldsm4(ah[sub], qH + aoff);
                ldsm4(al[sub], qL + aoff);
            }
            uint32_t bh[4][4], bl[4][4];
#pragma unroll
            for (int ng = 0; ng < 4; ng++) {
                int nrow = wn + ng * 16 + (lane & 7) + ((lane >> 4) << 3);
                int nch = ks * 2 + ((lane >> 3) & 1);
                uint32_t boff = (uint32_t)(nrow << 6) + (uint32_t)((nch ^ (nrow & 3)) << 4);
                ldsm4(bh[ng], kH + boff);
                ldsm4(bl[ng], kL + boff);
            }
#pragma unroll
            for (int sub = 0; sub < 2; sub++)
#pragma unroll
                for (int nt = 0; nt < 8; nt++) {
                    int ng = nt >> 1, hh = nt & 1;
                    uint32_t b0h = bh[ng][2 * hh], b1h = bh[ng][2 * hh + 1];
                    uint32_t b0l = bl[ng][2 * hh], b1l = bl[ng][2 * hh + 1];
                    mma16816(c[sub][nt], ah[sub], b0h, b1h);
                    mma16816(c[sub][nt], ah[sub], b0l, b1l);
                    mma16816(c[sub][nt], al[sub], b0h, b1h);
                }
        }
        __syncthreads();
    }

    float* Am = g_A + (size_t)m * NN * NN;
    float* Lm = g_LLm + (size_t)m * NN * NN;
    const float* mm = g_m + b * LL_;
#pragma unroll
    for (int sub = 0; sub < 2; sub++) {
        int row = i0 + wm + sub * 16 + (lane >> 2);
        float mi0 = mm[row], mi1 = mm[row + 8];
#pragma unroll
        for (int nt = 0; nt < 8; nt++) {
            int col = j0 + wn + nt * 8 + (lane & 3) * 2;
            float mj0 = mm[col], mj1 = mm[col + 1];
            float e00 = expf(fmaxf(c[sub][nt][0] - 50.f * (mi0 + mj0), -40.f));
            float e01 = expf(fmaxf(c[sub][nt][1] - 50.f * (mi0 + mj1), -40.f));
            float e10 = expf(fmaxf(c[sub][nt][2] - 50.f * (mi1 + mj0), -40.f));
            float e11 = expf(fmaxf(c[sub][nt][3] - 50.f * (mi1 + mj1), -40.f));
            *(float2*)&Am[(size_t)row * NN + col] = make_float2(e00, e01);
            *(float2*)&Am[(size_t)(row + 8) * NN + col] = make_float2(e10, e11);
            *(float2*)&Lm[(size_t)row * NN + col] = make_float2(-e00, -e01);
            *(float2*)&Lm[(size_t)(row + 8) * NN + col] = make_float2(-e10, -e11);
        }
    }
}

// ---------------- column sums of A; fix Laplacian diagonal in place ----------------
__global__ void k_colsum()
{
    int m = blockIdx.y;
    int j = blockIdx.x * 128 + threadIdx.x;
    const float* Am = g_A + (size_t)m * NN * NN;
    float s = 0.f;
    for (int i = 0; i < NN; i++) s += Am[i * NN + j];
    int b = m / HH;
    g_LLm[(size_t)m * NN * NN + (size_t)j * NN + j] += s + g_R[b * LL_ + j];
}

// ---------------- GJ step 1+2 fused: F-split, pivot inversion, rowscale ----------------
// One block per matrix m. Pivot numerics identical to previous k_pivot; rowscale
// computed from smem Pinv (identical math to previous k_rowscale, Ps == P).
__global__ __launch_bounds__(256) void k_pivot_rs(int kb)
{
    int m = blockIdx.x;
    float* A = g_LLm + (size_t)m * NN * NN;
    // F-panel split (before pivot block is overwritten)
    for (int t = threadIdx.x; t < NN * 64; t += 256) {
        int r = t >> 6, c = t & 63;
        float v = A[r * NN + kb * 64 + c];
        __nv_bfloat16 h, l;
        split_bf16(v, &h, &l);
        g_Fh[(size_t)m * NN * 64 + t] = h;
        g_Fl[(size_t)m * NN * 64 + t] = l;
    }
    __shared__ float P[64 * 65];
    __shared__ float s_col[64];
    __shared__ float s_piv;
    __shared__ __align__(16) float Ts[64 * 64];
    for (int t = threadIdx.x; t < 4096; t += 256) {
        int r = t >> 6, c = t & 63;
        P[r * 65 + c] = A[(kb * 64 + r) * NN + kb * 64 + c];
    }
    __syncthreads();
    for (int k = 0; k < 64; k++) {
        if (threadIdx.x == 0) s_piv = 1.0f / P[k * 65 + k];
        __syncthreads();
        if (threadIdx.x < 64) s_col[threadIdx.x] = P[threadIdx.x * 65 + k];
        __syncthreads();
        if (threadIdx.x < 64) {
            int j = threadIdx.x;
            P[k * 65 + j] = (j == k) ? s_piv : P[k * 65 + j] * s_piv;
        }
        __syncthreads();
        for (int t = threadIdx.x; t < 4096; t += 256) {
            int i = t >> 6, j = t & 63;
            if (i != k) {
                P[i * 65 + j] = (j == k) ? (-s_col[i] * s_piv)
                                         : P[i * 65 + j] - s_col[i] * P[k * 65 + j];
            }
        }
        __syncthreads();
    }
    // write Pinv back (fp32 + split into row panel)
    for (int t = threadIdx.x; t < 4096; t += 256) {
        int r = t >> 6, c = t & 63;
        float v = P[r * 65 + c];
        A[(kb * 64 + r) * NN + kb * 64 + c] = v;
        __nv_bfloat16 h, l;
        split_bf16(v, &h, &l);
        g_rowh[(size_t)m * 64 * NN + r * NN + kb * 64 + c] = h;
        g_rowl[(size_t)m * 64 * NN + r * NN + kb * 64 + c] = l;
    }
    // rowscale: Row[J] = Pinv @ A[K][J] for J != K, using smem Pinv
    int tx = threadIdx.x & 15, ty = threadIdx.x >> 4;
    for (int jt = 0; jt < 8; jt++) {
        if (jt == kb) continue;
        __syncthreads();
        for (int t = threadIdx.x; t < 4096; t += 256) {
            int r = t >> 6, c = t & 63;
            Ts[r * 64 + c] = A[(kb * 64 + r) * NN + jt * 64 + c];
        }
        __syncthreads();
        float acc[4][4] = {};
#pragma unroll
        for (int kk = 0; kk < 64; kk++) {
            float4 bv = *(float4*)&Ts[kk * 64 + tx * 4];
#pragma unroll
            for (int i = 0; i < 4; i++) {
                float a = P[(ty * 4 + i) * 65 + kk];
                acc[i][0] += a * bv.x; acc[i][1] += a * bv.y;
                acc[i][2] += a * bv.z; acc[i][3] += a * bv.w;
            }
        }
#pragma unroll
        for (int i = 0; i < 4; i++)
#pragma unroll
            for (int j = 0; j < 4; j++) {
                int r = ty * 4 + i, c = jt * 64 + tx * 4 + j;
                float v = acc[i][j];
                A[(kb * 64 + r) * NN + c] = v;
                __nv_bfloat16 h, l;
                split_bf16(v, &h, &l);
                g_rowh[(size_t)m * 64 * NN + r * NN + c] = h;
                g_rowl[(size_t)m * 64 * NN + r * NN + c] = l;
            }
    }
}

// step kernel 3 (HMMA): A[I][J] -= F @ Row[J]; A[I][K] = -F @ Pinv
// 64(i) x 128(j) output tile, k=64, 256 threads / 8 warps (16x64 per warp), 3-term split.
__global__ __launch_bounds__(256) void k_update_mma(int kb)
{
    __shared__ __align__(128) uint8_t sFh[8192], sFl[8192];
    __shared__ __align__(128) uint8_t sBh[16384], sBl[16384];
    int jt2 = blockIdx.x;                       // 0..3 -> cols jt2*128..+128
    int it = blockIdx.y; if (it >= kb) it++;    // skip kb
    int m = blockIdx.z;
    float* A = g_LLm + (size_t)m * NN * NN;
    int t = threadIdx.x;
    int w = t >> 5, lane = t & 31;

    uint32_t fH = smem_u32(sFh), fL = smem_u32(sFl);
    uint32_t bH = smem_u32(sBh), bL = smem_u32(sBl);

    const __nv_bfloat16* Fh = g_Fh + (size_t)m * NN * 64 + (size_t)it * 64 * 64;
    const __nv_bfloat16* Fl = g_Fl + (size_t)m * NN * 64 + (size_t)it * 64 * 64;
    const __nv_bfloat16* Rh = g_rowh + (size_t)m * 64 * NN + jt2 * 128;
    const __nv_bfloat16* Rl = g_rowl + (size_t)m * 64 * NN + jt2 * 128;

    for (int id = t; id < 512; id += 256) {
        int r = id >> 3, ch = id & 7;
        uint32_t off = (uint32_t)(r << 7) + (uint32_t)((ch ^ (r & 7)) << 4);
        cp16(fH + off, Fh + r * 64 + ch * 8);
        cp16(fL + off, Fl + r * 64 + ch * 8);
    }
    for (int id = t; id < 1024; id += 256) {
        int r = id >> 4, ch = id & 15;
        uint32_t off = (uint32_t)(r << 8) + (uint32_t)((ch ^ (r & 7)) << 4);
        cp16(bH + off, Rh + (size_t)r * NN + ch * 8);
        cp16(bL + off, Rl + (size_t)r * NN + ch * 8);
    }
    CP_COMMIT(); CP_WAIT0();
    __syncthreads();

    int wm = (w & 3) * 16, wn = (w >> 2) * 64;
    int lrow = (lane & 7) + ((lane >> 4) << 3);
    int lcol8 = (lane & 8) >> 3;

    float c[8][4];
#pragma unroll
    for (int i = 0; i < 8; i++)
#pragma unroll
        for (int v = 0; v < 4; v++) c[i][v] = 0.f;

#pragma unroll
    for (int ks = 0; ks < 4; ks++) {
        uint32_t ah[4], al[4];
        {
            int arow = wm + (lane & 15);
            int ach = (ks << 1) + (lane >> 4);
            uint32_t aoff = (uint32_t)(arow << 7) + (uint32_t)((ach ^ (arow & 7)) << 4);
            ldsm4(ah, fH + aoff);
            ldsm4(al, fL + aoff);
        }
        uint32_t bhf[4][4], blf[4][4];
        int r = (ks << 4) + lrow;
        int rx = r & 7;
#pragma unroll
        for (int ng = 0; ng < 4; ng++) {
            int colc = ((wn + ng * 16) >> 3) + lcol8;
            uint32_t boff = (uint32_t)(r << 8) + (uint32_t)((colc ^ rx) << 4);
            ldsm4t(bhf[ng], bH + boff);
            ldsm4t(blf[ng], bL + boff);
        }
#pragma unroll
        for (int ng = 0; ng < 4; ng++)
#pragma unroll
            for (int h = 0; h < 2; h++) {
                int nt = ng * 2 + h;
                mma16816(c[nt], ah, bhf[ng][h], bhf[ng][2 + h]);
                mma16816(c[nt], ah, blf[ng][h], blf[ng][2 + h]);
                mma16816(c[nt], al, bhf[ng][h], bhf[ng][2 + h]);
            }
    }

    int row = it * 64 + wm + (lane >> 2);
    int coff = (lane & 3) * 2;
    int jtile = jt2 * 2 + (wn >> 6);
    bool zero = (jtile == kb);
#pragma unroll
    for (int nt = 0; nt < 8; nt++) {
        int col = jt2 * 128 + wn + nt * 8 + coff;
        float* p0 = &A[(size_t)row * NN + col];
        float* p1 = &A[(size_t)(row + 8) * NN + col];
        float2 b0 = make_float2(0.f, 0.f), b1 = make_float2(0.f, 0.f);
        if (!zero) { b0 = *(float2*)p0; b1 = *(float2*)p1; }
        *(float2*)p0 = make_float2(b0.x - c[nt][0], b0.y - c[nt][1]);
        *(float2*)p1 = make_float2(b1.x - c[nt][2], b1.y - c[nt][3]);
    }
}

// ---------------- diag + d0 ----------------
__global__ void k_diag(float* __restrict__ out)
{
    int idx = blockIdx.x * 256 + threadIdx.x;
    int m = idx / NN, i = idx - m * NN;
    float dv = g_LLm[(size_t)m * NN * NN + (size_t)i * NN + i];
    g_diag[idx] = dv;
    int b = m / HH;
    out[OFF_D0 + idx] = g_R[b * LL_ + i] * dv;
}

// ---------------- d = A * (diag[j] - LLinv[j][i]); also masked bf16 split ----------------
// 64x64 tiles, 256 threads, 16 elements per thread.
__global__ __launch_bounds__(256) void k_dmat(float* __restrict__ out)
{
    int m = blockIdx.z, b = m / HH;
    int i0 = blockIdx.y * 64, j0 = blockIdx.x * 64;
    __shared__ float Ts[64 * 65];
    __shared__ float mi_s[64], mj_s[64];
    const float* Lm = g_LLm + (size_t)m * NN * NN;
    if (threadIdx.x < 64) mi_s[threadIdx.x] = g_m[b * LL_ + i0 + threadIdx.x];
    else if (threadIdx.x < 128) mj_s[threadIdx.x - 64] = g_m[b * LL_ + j0 + threadIdx.x - 64];
    for (int t = threadIdx.x; t < 4096; t += 256) {
        int r = t >> 6, c = t & 63;
        Ts[r * 65 + c] = Lm[(size_t)(j0 + r) * NN + i0 + c];   // Ts[j][i]
    }
    __syncthreads();
    const float* Am = g_A + (size_t)m * NN * NN;
    float* Dm = out + OFF_D + (size_t)m * NN * NN;
    for (int t = threadIdx.x; t < 4096; t += 256) {
        int li = t >> 6, lj = t & 63;
        int gi = i0 + li, gj = j0 + lj;
        float a = Am[(size_t)gi * NN + gj];
        float v = a * (g_diag[m * NN + gj] - Ts[lj * 65 + li]);
        Dm[(size_t)gi * NN + gj] = v;
        float vm = (mi_s[li] + mj_s[lj] != 0.0f) ? 0.0f : v;
        size_t idx = (size_t)m * NN * NN + (size_t)gi * NN + gj;
        __nv_bfloat16 h, l;
        split_bf16(vm, &h, &l);
        g_dh[idx] = h; g_dl[idx] = l;
    }
}

// ---------------- context via mma.sync bf16 split; double-buffered cp.async ----------------
#define CTX_STAGE 32768
#define CTX_SMEM  65536
__global__ __launch_bounds__(256) void k_context_mma(float* __restrict__ out)
{
    extern __shared__ __align__(128) uint8_t dsm[];
    int t = threadIdx.x;
    int m = blockIdx.z, b = m / HH;
    int q0 = blockIdx.y * 128, n0 = blockIdx.x * 128;
    const __nv_bfloat16* dh = g_dh + (size_t)m * NN * NN;
    const __nv_bfloat16* dl = g_dl + (size_t)m * NN * NN;
    const __nv_bfloat16* xh = g_xh + (size_t)b * LL_ * DD;
    const __nv_bfloat16* xl = g_xl + (size_t)b * LL_ * DD;
    uint32_t smem0 = smem_u32(dsm);

    int wid = t >> 5, lane = t & 31;
    int wm = (wid & 3) * 32;
    int wn = (wid >> 2) * 64;
    int lrow = (lane & 7) + ((lane >> 4) << 3);
    int lcol8 = (lane & 8) >> 3;

    float c[2][8][4];
#pragma unroll
    for (int i = 0; i < 2; i++)
#pragma unroll
        for (int j = 0; j < 8; j++)
#pragma unroll
            for (int v = 0; v < 4; v++) c[i][j][v] = 0.f;

    {
        uint32_t base = smem0;
#pragma unroll
        for (int rep = 0; rep < 2; rep++) {
            int id = t + rep * 256;
            int r = id >> 4, ch = id & 15;
            uint32_t off = (uint32_t)(r << 8) + (uint32_t)((ch ^ (r & 7)) << 4);
            cp16(base + off,         dh + (size_t)r * NN + q0 + ch * 8);
            cp16(base + 8192 + off,  dl + (size_t)r * NN + q0 + ch * 8);
            cp16(base + 16384 + off, xh + (size_t)r * DD + n0 + ch * 8);
            cp16(base + 24576 + off, xl + (size_t)r * DD + n0 + ch * 8);
        }
        CP_COMMIT();
    }

    for (int kc = 0; kc < 16; kc++) {
        if (kc < 15) {
            int k0 = (kc + 1) * 32;
            uint32_t base = smem0 + ((kc + 1) & 1) * CTX_STAGE;
#pragma unroll
            for (int rep = 0; rep < 2; rep++) {
                int id = t + rep * 256;
                int r = id >> 4, ch = id & 15;
                int kg = k0 + r;
                uint32_t off = (uint32_t)(r << 8) + (uint32_t)((ch ^ (r & 7)) << 4);
                cp16(base + off,         dh + (size_t)kg * NN + q0 + ch * 8);
                cp16(base + 8192 + off,  dl + (size_t)kg * NN + q0 + ch * 8);
                cp16(base + 16384 + off, xh + (size_t)kg * DD + n0 + ch * 8);
                cp16(base + 24576 + off, xl + (size_t)kg * DD + n0 + ch * 8);
            }
            CP_COMMIT();
            CP_WAIT1();
        } else {
            CP_WAIT0();
        }
        __syncthreads();

        uint32_t sb = smem0 + (kc & 1) * CTX_STAGE;
        uint32_t aHi = sb, aLo = sb + 8192, bHi = sb + 16384, bLo = sb + 24576;
#pragma unroll
        for (int ks = 0; ks < 32; ks += 16) {
            int r = ks + lrow;
            uint32_t rsw = (uint32_t)(r << 8);
            uint32_t rx = (uint32_t)(r & 7);
            uint32_t ah[2][4], al[2][4];
#pragma unroll
            for (int sub = 0; sub < 2; sub++) {
                uint32_t colc = (uint32_t)(((wm + sub * 16) >> 3) + lcol8);
                uint32_t boff = rsw + ((colc ^ rx) << 4);
                ldsm4t(ah[sub], aHi + boff);
                ldsm4t(al[sub], aLo + boff);
            }
            uint32_t bh[4][4], bl[4][4];
#pragma unroll
            for (int ng = 0; ng < 4; ng++) {
                uint32_t colc = (uint32_t)(((wn + ng * 16) >> 3) + lcol8);
                uint32_t boff = rsw + ((colc ^ rx) << 4);
                ldsm4t(bh[ng], bHi + boff);
                ldsm4t(bl[ng], bLo + boff);
            }
#pragma unroll
            for (int sub = 0; sub < 2; sub++) {
#pragma unroll
                for (int nt = 0; nt < 8; nt++) {
                    int ng = nt >> 1, h = nt & 1;
                    uint32_t b0h = bh[ng][h], b1h = bh[ng][2 + h];
                    uint32_t b0l = bl[ng][h], b1l = bl[ng][2 + h];
                    mma16816(c[sub][nt], ah[sub], b0h, b1h);
                    mma16816(c[sub][nt], ah[sub], b0l, b1l);
                    mma16816(c[sub][nt], al[sub], b0h, b1h);
                }
            }
        }
        __syncthreads();
    }

    float* Cm = out + OFF_CTX + (size_t)m * LL_ * DD;
#pragma unroll
    for (int sub = 0; sub < 2; sub++) {
        int q = q0 + wm + sub * 16 + (lane >> 2);
#pragma unroll
        for (int nt = 0; nt < 8; nt++) {
            int n = n0 + wn + nt * 8 + (lane & 3) * 2;
            *(float2*)&Cm[(size_t)q * DD + n] = make_float2(c[sub][nt][0], c[sub][nt][1]);
            *(float2*)&Cm[(size_t)(q + 8) * DD + n] = make_float2(c[sub][nt][2], c[sub][nt][3]);
        }
    }
}

// ---------------- BCE loss ----------------
__global__ void k_bce(const float* __restrict__ out, const int* __restrict__ labels)
{
    int idx = blockIdx.x * 256 + threadIdx.x;
    if (idx >= BB * LL_) return;
    int b = idx / LL_, i = idx - b * LL_;
    float y = (float)labels[idx];
    float s = 0.f;
    for (int h = 0; h < HH; h++) {
        float p = out[OFF_D0 + (b * HH + h) * LL_ + i];
        p = fminf(fmaxf(p, 1e-5f), 1.0f - 1e-5f);
        s += -(y * logf(p) + (1.0f - y) * logf(1.0f - p));
    }
    g_bce[idx] = y * s;
}

__global__ void k_loss(float* __restrict__ out)
{
    __shared__ float red[256];
    float s = 0.f;
    for (int t = threadIdx.x; t < BB * LL_; t += 256) s += g_bce[t];
    red[threadIdx.x] = s;
    __syncthreads();
    for (int o = 128; o > 0; o >>= 1) {
        if (threadIdx.x < o) red[threadIdx.x] += red[threadIdx.x + o];
        __syncthreads();
    }
    if (threadIdx.x == 0) out[OFF_LOSS] = red[0] / (float)(BB * LL_);
}

// ---------------- launch ----------------
extern "C" void kernel_launch(void* const* d_in, const int* in_sizes, int n_in,
                              void* d_out, int out_size)
{
    const float* x    = (const float*)d_in[0];
    const float* mask = (const float*)d_in[1];
    const int* roots_label = (const int*)d_in[2];
    const float* Wq = (const float*)d_in[4];
    const float* bq = (const float*)d_in[5];
    const float* Wk = (const float*)d_in[6];
    const float* bk = (const float*)d_in[7];
    const float* Wr = (const float*)d_in[8];
    const float* br = (const float*)d_in[9];
    float* out = (float*)d_out;

    cudaFuncSetAttribute(k_context_mma, cudaFuncAttributeMaxDynamicSharedMemorySize,
                         CTX_SMEM);

    k_xsplit<<<(BB * LL_ * DD) / 256, 256>>>(x);
    k_wsplit<<<(2 * DD * DD) / 256, 256>>>(Wq, Wk);
    k_root<<<512, 256>>>(x, Wr, br, mask);

    k_proj_mma<<<dim3(6, 64, 2), 256>>>(bq, bk);
    k_scores_mma<<<dim3(4, 4, MTOT), 256>>>();
    k_colsum<<<dim3(4, MTOT), 128>>>();

    for (int kb = 0; kb < 8; kb++) {
        k_pivot_rs<<<MTOT, 256>>>(kb);
        k_update_mma<<<dim3(4, 7, MTOT), 256>>>(kb);
    }

    k_diag<<<(MTOT * NN) / 256, 256>>>(out);
    k_dmat<<<dim3(8, 8, MTOT), 256>>>(out);
    k_context_mma<<<dim3(6, 4, MTOT), 256, CTX_SMEM>>>(out);
    k_bce<<<16, 256>>>(out, roots_label);
    k_loss<<<1, 256>>>(out);
}

// round 17
// speedup vs baseline: 1.0600x; 1.0600x over previous
#include <cuda_runtime.h>
#include <cuda_bf16.h>
#include <math.h>
#include <stdint.h>

// Problem dims
#define BB 8
#define LL_ 512
#define DD 768
#define HH 12
#define MTOT 96      // BB*HH
#define NN 512

// Output layout (flattened tuple concat)
#define OFF_CTX 0
#define OFF_D   37748736
#define OFF_D0  62914560
#define OFF_LOSS 62963712

// ---------------- scratch (device globals; no allocations allowed) ----------------
__device__ float g_R[BB * LL_];
__device__ float g_m[BB * LL_];
__device__ float g_A[MTOT * NN * NN];     // exp(scores)
__device__ float g_LLm[MTOT * NN * NN];   // Laplacian -> becomes inverse in place
__device__ float g_diag[MTOT * NN];
__device__ float g_bce[BB * LL_];
// bf16 split scratch
__device__ __nv_bfloat16 g_dh[MTOT * NN * NN];   // masked d, hi
__device__ __nv_bfloat16 g_dl[MTOT * NN * NN];   // masked d, lo
__device__ __nv_bfloat16 g_xh[BB * LL_ * DD];
__device__ __nv_bfloat16 g_xl[BB * LL_ * DD];
__device__ __nv_bfloat16 g_qh[BB * LL_ * DD];
__device__ __nv_bfloat16 g_ql[BB * LL_ * DD];
__device__ __nv_bfloat16 g_kh[BB * LL_ * DD];
__device__ __nv_bfloat16 g_kl[BB * LL_ * DD];
__device__ __nv_bfloat16 g_wqh[DD * DD];
__device__ __nv_bfloat16 g_wql[DD * DD];
__device__ __nv_bfloat16 g_wkh[DD * DD];
__device__ __nv_bfloat16 g_wkl[DD * DD];
__device__ __nv_bfloat16 g_Fh[MTOT * NN * 64];   // GJ column panel hi/lo
__device__ __nv_bfloat16 g_Fl[MTOT * NN * 64];
__device__ __nv_bfloat16 g_rowh[MTOT * 64 * NN]; // GJ scaled row panel hi/lo
__device__ __nv_bfloat16 g_rowl[MTOT * 64 * NN];

// ===================== mma.sync helpers (HMMA path; compute_103-safe) =====================
__device__ __forceinline__ uint32_t smem_u32(const void* p) {
    uint32_t a;
    asm("{ .reg .u64 t; cvta.to.shared.u64 t, %1; cvt.u32.u64 %0, t; }"
        : "=r"(a) : "l"(p));
    return a;
}

__device__ __forceinline__ void ldsm4(uint32_t* r, uint32_t addr) {
    asm volatile("ldmatrix.sync.aligned.m8n8.x4.shared.b16 {%0,%1,%2,%3}, [%4];"
                 : "=r"(r[0]), "=r"(r[1]), "=r"(r[2]), "=r"(r[3]) : "r"(addr));
}
__device__ __forceinline__ void ldsm4t(uint32_t* r, uint32_t addr) {
    asm volatile("ldmatrix.sync.aligned.m8n8.x4.trans.shared.b16 {%0,%1,%2,%3}, [%4];"
                 : "=r"(r[0]), "=r"(r[1]), "=r"(r[2]), "=r"(r[3]) : "r"(addr));
}

__device__ __forceinline__ void mma16816(float* c, const uint32_t* a,
                                         uint32_t b0, uint32_t b1) {
    asm volatile("mma.sync.aligned.m16n8k16.row.col.f32.bf16.bf16.f32 "
                 "{%0,%1,%2,%3}, {%4,%5,%6,%7}, {%8,%9}, {%0,%1,%2,%3};"
                 : "+f"(c[0]), "+f"(c[1]), "+f"(c[2]), "+f"(c[3])
                 : "r"(a[0]), "r"(a[1]), "r"(a[2]), "r"(a[3]), "r"(b0), "r"(b1));
}

__device__ __forceinline__ void cp16(uint32_t dst, const void* src) {
    asm volatile("{ .reg .u64 g; cvta.to.global.u64 g, %1; "
                 "cp.async.cg.shared.global [%0], [g], 16; }"
                 :: "r"(dst), "l"(src) : "memory");
}
#define CP_COMMIT() asm volatile("cp.async.commit_group;" ::: "memory")
#define CP_WAIT0()  asm volatile("cp.async.wait_group 0;" ::: "memory")
#define CP_WAIT1()  asm volatile("cp.async.wait_group 1;" ::: "memory")

__device__ __forceinline__ void split_bf16(float v, __nv_bfloat16* h, __nv_bfloat16* l) {
    __nv_bfloat16 hh = __float2bfloat16(v);
    *h = hh;
    *l = __float2bfloat16(v - __bfloat162float(hh));
}
__device__ __forceinline__ void split2(float v0, float v1, uint32_t* hp, uint32_t* lp) {
    __nv_bfloat16 h0, l0, h1, l1;
    split_bf16(v0, &h0, &l0);
    split_bf16(v1, &h1, &l1);
    *hp = (uint32_t)__bfloat16_as_ushort(h0) | ((uint32_t)__bfloat16_as_ushort(h1) << 16);
    *lp = (uint32_t)__bfloat16_as_ushort(l0) | ((uint32_t)__bfloat16_as_ushort(l1) << 16);
}

// ---------------- x -> bf16 hi/lo ----------------
__global__ void k_xsplit(const float* __restrict__ X)
{
    int idx = blockIdx.x * 256 + threadIdx.x;
    float v = X[idx];
    __nv_bfloat16 h, l;
    split_bf16(v, &h, &l);
    g_xh[idx] = h; g_xl[idx] = l;
}

// ---------------- Wq/Wk -> bf16 hi/lo ----------------
__global__ void k_wsplit(const float* __restrict__ Wq, const float* __restrict__ Wk)
{
    int idx = blockIdx.x * 256 + threadIdx.x;   // 2*768*768
    int which = idx >= DD * DD;
    int i = which ? idx - DD * DD : idx;
    float v = which ? Wk[i] : Wq[i];
    __nv_bfloat16 h, l;
    split_bf16(v, &h, &l);
    if (which) { g_wkh[i] = h; g_wkl[i] = l; }
    else       { g_wqh[i] = h; g_wql[i] = l; }
}

// ---------------- root scores + mask precompute ----------------
__global__ __launch_bounds__(256) void k_root(const float* __restrict__ X,
                                              const float* __restrict__ Wr,
                                              const float* __restrict__ br,
                                              const float* __restrict__ mask)
{
    int warp = (blockIdx.x * blockDim.x + threadIdx.x) >> 5;
    int lane = threadIdx.x & 31;
    if (warp >= BB * LL_) return;
    float s = 0.f;
    for (int t = lane; t < 768; t += 32) s += X[warp * 768 + t] * Wr[t];
#pragma unroll
    for (int o = 16; o > 0; o >>= 1) s += __shfl_down_sync(0xffffffff, s, o);
    if (lane == 0) {
        float m = mask[warp] * (-1.0f / 10000.0f);
        float root = fmaxf(s + br[0] - m * 50.0f, -40.0f);
        g_R[warp] = expf(root);
        g_m[warp] = m;
    }
}

// ---------------- projection via HMMA split: q/k = split((X@W + b)*scale) ----------------
__global__ __launch_bounds__(256) void k_proj_mma(const float* __restrict__ bq,
                                                  const float* __restrict__ bk)
{
    __shared__ __align__(128) uint8_t sAh[8192], sAl[8192], sBh[16384], sBl[16384];
    int t = threadIdx.x;
    int which = blockIdx.z;
    int m0 = blockIdx.y * 64, n0 = blockIdx.x * 128;
    const __nv_bfloat16* Wh = which ? g_wkh : g_wqh;
    const __nv_bfloat16* Wl = which ? g_wkl : g_wql;
    const float* bias = which ? bk : bq;
    float scale = which ? 1.0f : 0.03608439182435161f;   // 1/sqrt(768)
    __nv_bfloat16* dsth = which ? g_kh : g_qh;
    __nv_bfloat16* dstl = which ? g_kl : g_ql;

    uint32_t aH = smem_u32(sAh), aL = smem_u32(sAl);
    uint32_t bH = smem_u32(sBh), bL = smem_u32(sBl);

    int wid = t >> 5, lane = t & 31;
    int wm = (wid & 3) * 16, wn = (wid >> 2) * 64;
    int lrow = (lane & 7) + ((lane >> 4) << 3);
    int lcol8 = (lane & 8) >> 3;

    float c[8][4];
#pragma unroll
    for (int j = 0; j < 8; j++)
#pragma unroll
        for (int v = 0; v < 4; v++) c[j][v] = 0.f;

    for (int kc = 0; kc < 24; kc++) {
        int k0 = kc * 32;
#pragma unroll
        for (int rep = 0; rep < 6; rep++) {
            int id = t + rep * 256;   // 0..1535
            if (id < 512) {
                int buf = id >> 8, idx = id & 255;
                int r = idx >> 2, ch = idx & 3;
                uint32_t off = (uint32_t)(r << 7) + (uint32_t)((ch ^ (r & 7)) << 4);
                cp16((buf ? aL : aH) + off,
                     (buf ? g_xl : g_xh) + (size_t)(m0 + r) * DD + k0 + ch * 8);
            } else {
                int id2 = id - 512;
                int buf = id2 >> 9, idx = id2 & 511;
                int r = idx >> 4, ch = idx & 15;
                uint32_t off = (uint32_t)(r << 8) + (uint32_t)((ch ^ (r & 7)) << 4);
                cp16((buf ? bL : bH) + off,
                     (buf ? Wl : Wh) + (size_t)(k0 + r) * DD + n0 + ch * 8);
            }
        }
        CP_COMMIT(); CP_WAIT0();
        __syncthreads();

#pragma unroll
        for (int ks = 0; ks < 2; ks++) {
            uint32_t ah[4], al[4];
            {
                int arow = wm + (lane & 15);
                int ach = ks * 2 + (lane >> 4);
                uint32_t aoff = (uint32_t)(arow << 7) + (uint32_t)((ach ^ (arow & 7)) << 4);
                ldsm4(ah, aH + aoff);
                ldsm4(al, aL + aoff);
            }
            uint32_t bhf[4][4], blf[4][4];
            int r = ks * 16 + lrow;
            int rx = r & 7;
#pragma unroll
            for (int ng = 0; ng < 4; ng++) {
                int colc = ((wn + ng * 16) >> 3) + lcol8;
                uint32_t boff = (uint32_t)(r << 8) + (uint32_t)((colc ^ rx) << 4);
                ldsm4t(bhf[ng], bH + boff);
                ldsm4t(blf[ng], bL + boff);
            }
#pragma unroll
            for (int ng = 0; ng < 4; ng++)
#pragma unroll
                for (int h = 0; h < 2; h++) {
                    int nt = ng * 2 + h;
                    mma16816(c[nt], ah, bhf[ng][h], bhf[ng][2 + h]);
                    mma16816(c[nt], ah, blf[ng][h], blf[ng][2 + h]);
                    mma16816(c[nt], al, bhf[ng][h], bhf[ng][2 + h]);
                }
        }
        __syncthreads();
    }

    int row = m0 + wm + (lane >> 2);
#pragma unroll
    for (int nt = 0; nt < 8; nt++) {
        int col = n0 + wn + nt * 8 + (lane & 3) * 2;
        float b0 = bias[col], b1 = bias[col + 1];
        uint32_t hp, lp;
        split2((c[nt][0] + b0) * scale, (c[nt][1] + b1) * scale, &hp, &lp);
        *(uint32_t*)&dsth[(size_t)row * DD + col] = hp;
        *(uint32_t*)&dstl[(size_t)row * DD + col] = lp;
        split2((c[nt][2] + b0) * scale, (c[nt][3] + b1) * scale, &hp, &lp);
        *(uint32_t*)&dsth[(size_t)(row + 8) * DD + col] = hp;
        *(uint32_t*)&dstl[(size_t)(row + 8) * DD + col] = lp;
    }
}

// ---------------- scores via HMMA split: A = exp(clip(q.k^T - masks, -40)); LL = -A ----
__global__ __launch_bounds__(256) void k_scores_mma()
{
    __shared__ __align__(128) uint8_t sQh[8192], sQl[8192], sKh[8192], sKl[8192];
    int t = threadIdx.x;
    int m = blockIdx.z, b = m / HH, h = m % HH;
    int i0 = blockIdx.y * 128, j0 = blockIdx.x * 128;
    size_t qbase = (size_t)b * LL_ * DD + h * 64;

    uint32_t qH = smem_u32(sQh), qL = smem_u32(sQl);
    uint32_t kH = smem_u32(sKh), kL = smem_u32(sKl);

    int wid = t >> 5, lane = t & 31;
    int wm = (wid & 3) * 32, wn = (wid >> 2) * 64;

    float c[2][8][4];
#pragma unroll
    for (int i = 0; i < 2; i++)
#pragma unroll
        for (int j = 0; j < 8; j++)
#pragma unroll
            for (int v = 0; v < 4; v++) c[i][j][v] = 0.f;

    for (int kc = 0; kc < 2; kc++) {
        int k0 = kc * 32;
#pragma unroll
        for (int rep = 0; rep < 8; rep++) {
            int id = t + rep * 256;
            int half = id >> 10;          // 0=Q, 1=K
            int buf = (id >> 9) & 1;      // 0=hi, 1=lo
            int idx = id & 511;
            int r = idx >> 2, ch = idx & 3;
            uint32_t off = (uint32_t)(r << 6) + (uint32_t)((ch ^ (r & 3)) << 4);
            const __nv_bfloat16* src;
            uint32_t dst;
            if (half == 0) {
                src = (buf ? g_ql : g_qh) + qbase + (size_t)(i0 + r) * DD + k0 + ch * 8;
                dst = (buf ? qL : qH) + off;
            } else {
                src = (buf ? g_kl : g_kh) + qbase + (size_t)(j0 + r) * DD + k0 + ch * 8;
                dst = (buf ? kL : kH) + off;
            }
            cp16(dst, src);
        }
        CP_COMMIT(); CP_WAIT0();
        __syncthreads();

#pragma unroll
        for (int ks = 0; ks < 2; ks++) {
            uint32_t ah[2][4], al[2][4];
#pragma unroll
            for (int sub = 0; sub < 2; sub++) {
                int arow = wm + sub * 16 + (lane & 15);
                int ach = ks * 2 + (lane >> 4);
                uint32_t aoff = (uint32_t)(arow << 6) + (uint32_t)((ach ^ (arow & 3)) << 4);
                ldsm4(ah[sub], qH + aoff);
                ldsm4(al[sub], qL + aoff);
            }
            uint32_t bh[4][4], bl[4][4];
#pragma unroll
            for (int ng = 0; ng < 4; ng++) {
                int nrow = wn + ng * 16 + (lane & 7) + ((lane >> 4) << 3);
                int nch = ks * 2 + ((lane >> 3) & 1);
                uint32_t boff = (uint32_t)(nrow << 6) + (uint32_t)((nch ^ (nrow & 3)) << 4);
                ldsm4(bh[ng], kH + boff);
                ldsm4(bl[ng], kL + boff);
            }
#pragma unroll
            for (int sub = 0; sub < 2; sub++)
#pragma unroll
                for (int nt = 0; nt < 8; nt++) {
                    int ng = nt >> 1, hh = nt & 1;
                    uint32_t b0h = bh[ng][2 * hh], b1h = bh[ng][2 * hh + 1];
                    uint32_t b0l = bl[ng][2 * hh], b1l = bl[ng][2 * hh + 1];
                    mma16816(c[sub][nt], ah[sub], b0h, b1h);
                    mma16816(c[sub][nt], ah[sub], b0l, b1l);
                    mma16816(c[sub][nt], al[sub], b0h, b1h);
                }
        }
        __syncthreads();
    }

    float* Am = g_A + (size_t)m * NN * NN;
    float* Lm = g_LLm + (size_t)m * NN * NN;
    const float* mm = g_m + b * LL_;
#pragma unroll
    for (int sub = 0; sub < 2; sub++) {
        int row = i0 + wm + sub * 16 + (lane >> 2);
        float mi0 = mm[row], mi1 = mm[row + 8];
#pragma unroll
        for (int nt = 0; nt < 8; nt++) {
            int col = j0 + wn + nt * 8 + (lane & 3) * 2;
            float mj0 = mm[col], mj1 = mm[col + 1];
            float e00 = expf(fmaxf(c[sub][nt][0] - 50.f * (mi0 + mj0), -40.f));
            float e01 = expf(fmaxf(c[sub][nt][1] - 50.f * (mi0 + mj1), -40.f));
            float e10 = expf(fmaxf(c[sub][nt][2] - 50.f * (mi1 + mj0), -40.f));
            float e11 = expf(fmaxf(c[sub][nt][3] - 50.f * (mi1 + mj1), -40.f));
            *(float2*)&Am[(size_t)row * NN + col] = make_float2(e00, e01);
            *(float2*)&Am[(size_t)(row + 8) * NN + col] = make_float2(e10, e11);
            *(float2*)&Lm[(size_t)row * NN + col] = make_float2(-e00, -e01);
            *(float2*)&Lm[(size_t)(row + 8) * NN + col] = make_float2(-e10, -e11);
        }
    }
}

// ---------------- column sums of A; fix Laplacian diagonal in place ----------------
__global__ void k_colsum()
{
    int m = blockIdx.y;
    int j = blockIdx.x * 128 + threadIdx.x;
    const float* Am = g_A + (size_t)m * NN * NN;
    float s = 0.f;
    for (int i = 0; i < NN; i++) s += Am[i * NN + j];
    int b = m / HH;
    g_LLm[(size_t)m * NN * NN + (size_t)j * NN + j] += s + g_R[b * LL_ + j];
}

// ---------------- blocked Gauss-Jordan inversion, NB=64, 8 steps ----------------
__global__ __launch_bounds__(256) void k_pivot(int kb)
{
    int m = blockIdx.x;
    float* A = g_LLm + (size_t)m * NN * NN;
    for (int t = threadIdx.x; t < NN * 64; t += 256) {
        int r = t >> 6, c = t & 63;
        float v = A[r * NN + kb * 64 + c];
        __nv_bfloat16 h, l;
        split_bf16(v, &h, &l);
        g_Fh[(size_t)m * NN * 64 + t] = h;
        g_Fl[(size_t)m * NN * 64 + t] = l;
    }
    __shared__ float P[64 * 65];
    __shared__ float s_col[64];
    __shared__ float s_piv;
    for (int t = threadIdx.x; t < 4096; t += 256) {
        int r = t >> 6, c = t & 63;
        P[r * 65 + c] = A[(kb * 64 + r) * NN + kb * 64 + c];
    }
    __syncthreads();
    for (int k = 0; k < 64; k++) {
        if (threadIdx.x == 0) s_piv = 1.0f / P[k * 65 + k];
        __syncthreads();
        if (threadIdx.x < 64) s_col[threadIdx.x] = P[threadIdx.x * 65 + k];
        __syncthreads();
        if (threadIdx.x < 64) {
            int j = threadIdx.x;
            P[k * 65 + j] = (j == k) ? s_piv : P[k * 65 + j] * s_piv;
        }
        __syncthreads();
        for (int t = threadIdx.x; t < 4096; t += 256) {
            int i = t >> 6, j = t & 63;
            if (i != k) {
                P[i * 65 + j] = (j == k) ? (-s_col[i] * s_piv)
                                         : P[i * 65 + j] - s_col[i] * P[k * 65 + j];
            }
        }
        __syncthreads();
    }
    for (int t = threadIdx.x; t < 4096; t += 256) {
        int r = t >> 6, c = t & 63;
        float v = P[r * 65 + c];
        A[(kb * 64 + r) * NN + kb * 64 + c] = v;
        __nv_bfloat16 h, l;
        split_bf16(v, &h, &l);
        g_rowh[(size_t)m * 64 * NN + r * NN + kb * 64 + c] = h;
        g_rowl[(size_t)m * 64 * NN + r * NN + kb * 64 + c] = l;
    }
}

// step kernel 2 (fp32): row-block scale A[K][J] = Pinv @ A[K][J] (J != K) + bf16 split
__global__ __launch_bounds__(256) void k_rowscale(int kb)
{
    int jt = blockIdx.x; if (jt >= kb) jt++;
    int m = blockIdx.y;
    float* A = g_LLm + (size_t)m * NN * NN;
    __shared__ float Ps[64 * 65];
    __shared__ __align__(16) float Ts[64 * 64];
    for (int t = threadIdx.x; t < 4096; t += 256) {
        int r = t >> 6, c = t & 63;
        Ps[r * 65 + c] = A[(kb * 64 + r) * NN + kb * 64 + c];
        Ts[r * 64 + c] = A[(kb * 64 + r) * NN + jt * 64 + c];
    }
    __syncthreads();
    int tx = threadIdx.x & 15, ty = threadIdx.x >> 4;
    float acc[4][4] = {};
#pragma unroll
    for (int kk = 0; kk < 64; kk++) {
        float4 bv = *(float4*)&Ts[kk * 64 + tx * 4];
#pragma unroll
        for (int i = 0; i < 4; i++) {
            float a = Ps[(ty * 4 + i) * 65 + kk];
            acc[i][0] += a * bv.x; acc[i][1] += a * bv.y;
            acc[i][2] += a * bv.z; acc[i][3] += a * bv.w;
        }
    }
#pragma unroll
    for (int i = 0; i < 4; i++)
#pragma unroll
        for (int j = 0; j < 4; j++) {
            int r = ty * 4 + i, c = jt * 64 + tx * 4 + j;
            float v = acc[i][j];
            A[(kb * 64 + r) * NN + c] = v;
            __nv_bfloat16 h, l;
            split_bf16(v, &h, &l);
            g_rowh[(size_t)m * 64 * NN + r * NN + c] = h;
            g_rowl[(size_t)m * 64 * NN + r * NN + c] = l;
        }
}

// step kernel 3 (HMMA): A[I][J] -= F @ Row[J]; A[I][K] = -F @ Pinv
// 64(i) x 128(j) output tile, k=64, 256 threads / 8 warps (16x64 per warp), 3-term split.
__global__ __launch_bounds__(256) void k_update_mma(int kb)
{
    __shared__ __align__(128) uint8_t sFh[8192], sFl[8192];
    __shared__ __align__(128) uint8_t sBh[16384], sBl[16384];
    int jt2 = blockIdx.x;                       // 0..3 -> cols jt2*128..+128
    int it = blockIdx.y; if (it >= kb) it++;    // skip kb
    int m = blockIdx.z;
    float* A = g_LLm + (size_t)m * NN * NN;
    int t = threadIdx.x;
    int w = t >> 5, lane = t & 31;

    uint32_t fH = smem_u32(sFh), fL = smem_u32(sFl);
    uint32_t bH = smem_u32(sBh), bL = smem_u32(sBl);

    const __nv_bfloat16* Fh = g_Fh + (size_t)m * NN * 64 + (size_t)it * 64 * 64;
    const __nv_bfloat16* Fl = g_Fl + (size_t)m * NN * 64 + (size_t)it * 64 * 64;
    const __nv_bfloat16* Rh = g_rowh + (size_t)m * 64 * NN + jt2 * 128;
    const __nv_bfloat16* Rl = g_rowl + (size_t)m * 64 * NN + jt2 * 128;

    for (int id = t; id < 512; id += 256) {
        int r = id >> 3, ch = id & 7;
        uint32_t off = (uint32_t)(r << 7) + (uint32_t)((ch ^ (r & 7)) << 4);
        cp16(fH + off, Fh + r * 64 + ch * 8);
        cp16(fL + off, Fl + r * 64 + ch * 8);
    }
    for (int id = t; id < 1024; id += 256) {
        int r = id >> 4, ch = id & 15;
        uint32_t off = (uint32_t)(r << 8) + (uint32_t)((ch ^ (r & 7)) << 4);
        cp16(bH + off, Rh + (size_t)r * NN + ch * 8);
        cp16(bL + off, Rl + (size_t)r * NN + ch * 8);
    }
    CP_COMMIT(); CP_WAIT0();
    __syncthreads();

    int wm = (w & 3) * 16, wn = (w >> 2) * 64;
    int lrow = (lane & 7) + ((lane >> 4) << 3);
    int lcol8 = (lane & 8) >> 3;

    float c[8][4];
#pragma unroll
    for (int i = 0; i < 8; i++)
#pragma unroll
        for (int v = 0; v < 4; v++) c[i][v] = 0.f;

#pragma unroll
    for (int ks = 0; ks < 4; ks++) {
        uint32_t ah[4], al[4];
        {
            int arow = wm + (lane & 15);
            int ach = (ks << 1) + (lane >> 4);
            uint32_t aoff = (uint32_t)(arow << 7) + (uint32_t)((ach ^ (arow & 7)) << 4);
            ldsm4(ah, fH + aoff);
            ldsm4(al, fL + aoff);
        }
        uint32_t bhf[4][4], blf[4][4];
        int r = (ks << 4) + lrow;
        int rx = r & 7;
#pragma unroll
        for (int ng = 0; ng < 4; ng++) {
            int colc = ((wn + ng * 16) >> 3) + lcol8;
            uint32_t boff = (uint32_t)(r << 8) + (uint32_t)((colc ^ rx) << 4);
            ldsm4t(bhf[ng], bH + boff);
            ldsm4t(blf[ng], bL + boff);
        }
#pragma unroll
        for (int ng = 0; ng < 4; ng++)
#pragma unroll
            for (int h = 0; h < 2; h++) {
                int nt = ng * 2 + h;
                mma16816(c[nt], ah, bhf[ng][h], bhf[ng][2 + h]);
                mma16816(c[nt], ah, blf[ng][h], blf[ng][2 + h]);
                mma16816(c[nt], al, bhf[ng][h], bhf[ng][2 + h]);
            }
    }

    int row = it * 64 + wm + (lane >> 2);
    int coff = (lane & 3) * 2;
    int jtile = jt2 * 2 + (wn >> 6);
    bool zero = (jtile == kb);
#pragma unroll
    for (int nt = 0; nt < 8; nt++) {
        int col = jt2 * 128 + wn + nt * 8 + coff;
        float* p0 = &A[(size_t)row * NN + col];
        float* p1 = &A[(size_t)(row + 8) * NN + col];
        float2 b0 = make_float2(0.f, 0.f), b1 = make_float2(0.f, 0.f);
        if (!zero) { b0 = *(float2*)p0; b1 = *(float2*)p1; }
        *(float2*)p0 = make_float2(b0.x - c[nt][0], b0.y - c[nt][1]);
        *(float2*)p1 = make_float2(b1.x - c[nt][2], b1.y - c[nt][3]);
    }
}

// ---------------- diag + d0 ----------------
__global__ void k_diag(float* __restrict__ out)
{
    int idx = blockIdx.x * 256 + threadIdx.x;
    int m = idx / NN, i = idx - m * NN;
    float dv = g_LLm[(size_t)m * NN * NN + (size_t)i * NN + i];
    g_diag[idx] = dv;
    int b = m / HH;
    out[OFF_D0 + idx] = g_R[b * LL_ + i] * dv;
}

// ---------------- d = A * (diag[j] - LLinv[j][i]); also masked bf16 split ----------------
// 64x64 tiles, 256 threads, 16 elements per thread.
__global__ __launch_bounds__(256) void k_dmat(float* __restrict__ out)
{
    int m = blockIdx.z, b = m / HH;
    int i0 = blockIdx.y * 64, j0 = blockIdx.x * 64;
    __shared__ float Ts[64 * 65];
    __shared__ float mi_s[64], mj_s[64];
    const float* Lm = g_LLm + (size_t)m * NN * NN;
    if (threadIdx.x < 64) mi_s[threadIdx.x] = g_m[b * LL_ + i0 + threadIdx.x];
    else if (threadIdx.x < 128) mj_s[threadIdx.x - 64] = g_m[b * LL_ + j0 + threadIdx.x - 64];
    for (int t = threadIdx.x; t < 4096; t += 256) {
        int r = t >> 6, c = t & 63;
        Ts[r * 65 + c] = Lm[(size_t)(j0 + r) * NN + i0 + c];   // Ts[j][i]
    }
    __syncthreads();
    const float* Am = g_A + (size_t)m * NN * NN;
    float* Dm = out + OFF_D + (size_t)m * NN * NN;
    for (int t = threadIdx.x; t < 4096; t += 256) {
        int li = t >> 6, lj = t & 63;
        int gi = i0 + li, gj = j0 + lj;
        float a = Am[(size_t)gi * NN + gj];
        float v = a * (g_diag[m * NN + gj] - Ts[lj * 65 + li]);
        Dm[(size_t)gi * NN + gj] = v;
        float vm = (mi_s[li] + mj_s[lj] != 0.0f) ? 0.0f : v;
        size_t idx = (size_t)m * NN * NN + (size_t)gi * NN + gj;
        __nv_bfloat16 h, l;
        split_bf16(vm, &h, &l);
        g_dh[idx] = h; g_dl[idx] = l;
    }
}

// ---------------- context via mma.sync bf16 split; double-buffered cp.async ----------------
#define CTX_STAGE 32768
#define CTX_SMEM  65536
__global__ __launch_bounds__(256) void k_context_mma(float* __restrict__ out)
{
    extern __shared__ __align__(128) uint8_t dsm[];
    int t = threadIdx.x;
    int m = blockIdx.z, b = m / HH;
    int q0 = blockIdx.y * 128, n0 = blockIdx.x * 128;
    const __nv_bfloat16* dh = g_dh + (size_t)m * NN * NN;
    const __nv_bfloat16* dl = g_dl + (size_t)m * NN * NN;
    const __nv_bfloat16* xh = g_xh + (size_t)b * LL_ * DD;
    const __nv_bfloat16* xl = g_xl + (size_t)b * LL_ * DD;
    uint32_t smem0 = smem_u32(dsm);

    int wid = t >> 5, lane = t & 31;
    int wm = (wid & 3) * 32;
    int wn = (wid >> 2) * 64;
    int lrow = (lane & 7) + ((lane >> 4) << 3);
    int lcol8 = (lane & 8) >> 3;

    float c[2][8][4];
#pragma unroll
    for (int i = 0; i < 2; i++)
#pragma unroll
        for (int j = 0; j < 8; j++)
#pragma unroll
            for (int v = 0; v < 4; v++) c[i][j][v] = 0.f;

    {
        uint32_t base = smem0;
#pragma unroll
        for (int rep = 0; rep < 2; rep++) {
            int id = t + rep * 256;
            int r = id >> 4, ch = id & 15;
            uint32_t off = (uint32_t)(r << 8) + (uint32_t)((ch ^ (r & 7)) << 4);
            cp16(base + off,         dh + (size_t)r * NN + q0 + ch * 8);
            cp16(base + 8192 + off,  dl + (size_t)r * NN + q0 + ch * 8);
            cp16(base + 16384 + off, xh + (size_t)r * DD + n0 + ch * 8);
            cp16(base + 24576 + off, xl + (size_t)r * DD + n0 + ch * 8);
        }
        CP_COMMIT();
    }

    for (int kc = 0; kc < 16; kc++) {
        if (kc < 15) {
            int k0 = (kc + 1) * 32;
            uint32_t base = smem0 + ((kc + 1) & 1) * CTX_STAGE;
#pragma unroll
            for (int rep = 0; rep < 2; rep++) {
                int id = t + rep * 256;
                int r = id >> 4, ch = id & 15;
                int kg = k0 + r;
                uint32_t off = (uint32_t)(r << 8) + (uint32_t)((ch ^ (r & 7)) << 4);
                cp16(base + off,         dh + (size_t)kg * NN + q0 + ch * 8);
                cp16(base + 8192 + off,  dl + (size_t)kg * NN + q0 + ch * 8);
                cp16(base + 16384 + off, xh + (size_t)kg * DD + n0 + ch * 8);
                cp16(base + 24576 + off, xl + (size_t)kg * DD + n0 + ch * 8);
            }
            CP_COMMIT();
            CP_WAIT1();
        } else {
            CP_WAIT0();
        }
        __syncthreads();

        uint32_t sb = smem0 + (kc & 1) * CTX_STAGE;
        uint32_t aHi = sb, aLo = sb + 8192, bHi = sb + 16384, bLo = sb + 24576;
#pragma unroll
        for (int ks = 0; ks < 32; ks += 16) {
            int r = ks + lrow;
            uint32_t rsw = (uint32_t)(r << 8);
            uint32_t rx = (uint32_t)(r & 7);
            uint32_t ah[2][4], al[2][4];
#pragma unroll
            for (int sub = 0; sub < 2; sub++) {
                uint32_t colc = (uint32_t)(((wm + sub * 16) >> 3) + lcol8);
                uint32_t boff = rsw + ((colc ^ rx) << 4);
                ldsm4t(ah[sub], aHi + boff);
                ldsm4t(al[sub], aLo + boff);
            }
            uint32_t bh[4][4], bl[4][4];
#pragma unroll
            for (int ng = 0; ng < 4; ng++) {
                uint32_t colc = (uint32_t)(((wn + ng * 16) >> 3) + lcol8);
                uint32_t boff = rsw + ((colc ^ rx) << 4);
                ldsm4t(bh[ng], bHi + boff);
                ldsm4t(bl[ng], bLo + boff);
            }
#pragma unroll
            for (int sub = 0; sub < 2; sub++) {
#pragma unroll
                for (int nt = 0; nt < 8; nt++) {
                    int ng = nt >> 1, h = nt & 1;
                    uint32_t b0h = bh[ng][h], b1h = bh[ng][2 + h];
                    uint32_t b0l = bl[ng][h], b1l = bl[ng][2 + h];
                    mma16816(c[sub][nt], ah[sub], b0h, b1h);
                    mma16816(c[sub][nt], ah[sub], b0l, b1l);
                    mma16816(c[sub][nt], al[sub], b0h, b1h);
                }
            }
        }
        __syncthreads();
    }

    float* Cm = out + OFF_CTX + (size_t)m * LL_ * DD;
#pragma unroll
    for (int sub = 0; sub < 2; sub++) {
        int q = q0 + wm + sub * 16 + (lane >> 2);
#pragma unroll
        for (int nt = 0; nt < 8; nt++) {
            int n = n0 + wn + nt * 8 + (lane & 3) * 2;
            *(float2*)&Cm[(size_t)q * DD + n] = make_float2(c[sub][nt][0], c[sub][nt][1]);
            *(float2*)&Cm[(size_t)(q + 8) * DD + n] = make_float2(c[sub][nt][2], c[sub][nt][3]);
        }
    }
}

// ---------------- BCE loss ----------------
__global__ void k_bce(const float* __restrict__ out, const int* __restrict__ labels)
{
    int idx = blockIdx.x * 256 + threadIdx.x;
    if (idx >= BB * LL_) return;
    int b = idx / LL_, i = idx - b * LL_;
    float y = (float)labels[idx];
    float s = 0.f;
    for (int h = 0; h < HH; h++) {
        float p = out[OFF_D0 + (b * HH + h) * LL_ + i];
        p = fminf(fmaxf(p, 1e-5f), 1.0f - 1e-5f);
        s += -(y * logf(p) + (1.0f - y) * logf(1.0f - p));
    }
    g_bce[idx] = y * s;
}

__global__ void k_loss(float* __restrict__ out)
{
    __shared__ float red[256];
    float s = 0.f;
    for (int t = threadIdx.x; t < BB * LL_; t += 256) s += g_bce[t];
    red[threadIdx.x] = s;
    __syncthreads();
    for (int o = 128; o > 0; o >>= 1) {
        if (threadIdx.x < o) red[threadIdx.x] += red[threadIdx.x + o];
        __syncthreads();
    }
    if (threadIdx.x == 0) out[OFF_LOSS] = red[0] / (float)(BB * LL_);
}

// ---------------- launch ----------------
extern "C" void kernel_launch(void* const* d_in, const int* in_sizes, int n_in,
                              void* d_out, int out_size)
{
    const float* x    = (const float*)d_in[0];
    const float* mask = (const float*)d_in[1];
    const int* roots_label = (const int*)d_in[2];
    const float* Wq = (const float*)d_in[4];
    const float* bq = (const float*)d_in[5];
    const float* Wk = (const float*)d_in[6];
    const float* bk = (const float*)d_in[7];
    const float* Wr = (const float*)d_in[8];
    const float* br = (const float*)d_in[9];
    float* out = (float*)d_out;

    cudaFuncSetAttribute(k_context_mma, cudaFuncAttributeMaxDynamicSharedMemorySize,
                         CTX_SMEM);

    k_xsplit<<<(BB * LL_ * DD) / 256, 256>>>(x);
    k_wsplit<<<(2 * DD * DD) / 256, 256>>>(Wq, Wk);
    k_root<<<512, 256>>>(x, Wr, br, mask);

    k_proj_mma<<<dim3(6, 64, 2), 256>>>(bq, bk);
    k_scores_mma<<<dim3(4, 4, MTOT), 256>>>();
    k_colsum<<<dim3(4, MTOT), 128>>>();

    for (int kb = 0; kb < 8; kb++) {
        k_pivot<<<MTOT, 256>>>(kb);
        k_rowscale<<<dim3(7, MTOT), 256>>>(kb);
        k_update_mma<<<dim3(4, 7, MTOT), 256>>>(kb);
    }

    k_diag<<<(MTOT * NN) / 256, 256>>>(out);
    k_dmat<<<dim3(8, 8, MTOT), 256>>>(out);
    k_context_mma<<<dim3(6, 4, MTOT), 256, CTX_SMEM>>>(out);
    k_bce<<<16, 256>>>(out, roots_label);
    k_loss<<<1, 256>>>(out);
}